// round 3
// baseline (speedup 1.0000x reference)
#include <cuda_runtime.h>

#define NN 100000
#define MM 32
#define DD 3
#define BB 8

// Scratch: fs transposed to [n][d][b] layout. float4 array -> structurally
// 16B-aligned for LDG.128/STG.128. 6 float4 per node row = 96 B.
__device__ float4 g_fst4[NN * 6];

// Flag: 1 if stencil_indices buffer is int64, 0 if int32.
__device__ int g_idx_is64;

// ---------------------------------------------------------------------------
// Kernel 0: detect index dtype. jax with x64 disabled silently downgrades
// jnp.int64 -> int32, so the buffer may be either. For little-endian int64
// values in [0, N) every odd 32-bit word is 0; for int32 random indices the
// odd words are independent indices (≈ never all zero). Deterministic.
// ---------------------------------------------------------------------------
__global__ void detect_idx_kernel(const int* __restrict__ idx32) {
    int all_zero = 1;
#pragma unroll
    for (int k = 0; k < 64; k++) {
        if (idx32[2 * k + 1] != 0) { all_zero = 0; break; }
    }
    g_idx_is64 = all_zero;
}

// ---------------------------------------------------------------------------
// Kernel 1: transpose fs (B,N,D) -> fs_t (N,D,B). One thread per (n,d).
// ---------------------------------------------------------------------------
__global__ void __launch_bounds__(256) transpose_fs_kernel(const float* __restrict__ fs) {
    int t = blockIdx.x * 256 + threadIdx.x;   // t = n*3 + d
    if (t >= NN * DD) return;
    float v[BB];
#pragma unroll
    for (int b = 0; b < BB; b++) v[b] = __ldg(fs + (size_t)b * (NN * DD) + t);
    int n = t / DD;
    int d = t - n * DD;
    float4* dst = g_fst4 + (size_t)n * 6 + d * 2;
    dst[0] = make_float4(v[0], v[1], v[2], v[3]);
    dst[1] = make_float4(v[4], v[5], v[6], v[7]);
}

// ---------------------------------------------------------------------------
// Kernel 2: main gather + contraction.
// 8 lanes per node. Lane lig handles m in {lig, lig+8, lig+16, lig+24}.
// Each gather pulls a 96B fs_t row (all d, all b) -> 24 FMAs.
// Value-routed butterfly (7 shfl + 7 add) leaves batch b's sum on lane b.
// ---------------------------------------------------------------------------
__global__ void __launch_bounds__(256) rbffd_main_kernel(
    const float* __restrict__ w,        // (N, D, M) f32
    const int* __restrict__ idx32,      // (N, M) int32 or int64-as-int32-pairs
    float* __restrict__ out)            // (B, N) f32
{
    int tid  = blockIdx.x * 256 + threadIdx.x;
    int node = tid >> 3;
    if (node >= NN) return;
    int lane = threadIdx.x & 31;
    int lig  = lane & 7;

    int is64   = g_idx_is64;
    int stride = is64 ? 2 : 1;
    const int* irow = idx32 + (size_t)node * MM * stride;
    const float* wrow = w + (size_t)node * (DD * MM);

    // Fetch this lane's 4 stencil indices (clamped defensively).
    int ii[4];
#pragma unroll
    for (int k = 0; k < 4; k++) {
        int v = __ldg(irow + (lig + 8 * k) * stride);
        ii[k] = ((unsigned)v < (unsigned)NN) ? v : 0;
    }

    float acc[BB];
#pragma unroll
    for (int b = 0; b < BB; b++) acc[b] = 0.0f;

#pragma unroll
    for (int k = 0; k < 4; k++) {
        int m = lig + 8 * k;
        float w0 = __ldg(wrow + m);
        float w1 = __ldg(wrow + MM + m);
        float w2 = __ldg(wrow + 2 * MM + m);

        const float4* row = g_fst4 + (size_t)ii[k] * 6;   // 96B row: [d][b]
        float4 a0 = row[0];   // d0, b0..3
        float4 a1 = row[1];   // d0, b4..7
        float4 a2 = row[2];   // d1, b0..3
        float4 a3 = row[3];   // d1, b4..7
        float4 a4 = row[4];   // d2, b0..3
        float4 a5 = row[5];   // d2, b4..7

        acc[0] += w0 * a0.x + w1 * a2.x + w2 * a4.x;
        acc[1] += w0 * a0.y + w1 * a2.y + w2 * a4.y;
        acc[2] += w0 * a0.z + w1 * a2.z + w2 * a4.z;
        acc[3] += w0 * a0.w + w1 * a2.w + w2 * a4.w;
        acc[4] += w0 * a1.x + w1 * a3.x + w2 * a5.x;
        acc[5] += w0 * a1.y + w1 * a3.y + w2 * a5.y;
        acc[6] += w0 * a1.z + w1 * a3.z + w2 * a5.z;
        acc[7] += w0 * a1.w + w1 * a3.w + w2 * a5.w;
    }

    // Value-routed butterfly across the 8 lanes of this node group.
    const unsigned FULL = 0xffffffffu;
    bool hiA = (lane & 4) != 0;
    float t4[4];
#pragma unroll
    for (int j = 0; j < 4; j++) {
        float send = hiA ? acc[j] : acc[j + 4];
        float recv = __shfl_xor_sync(FULL, send, 4);
        t4[j] = (hiA ? acc[j + 4] : acc[j]) + recv;
    }
    bool hiB = (lane & 2) != 0;
    float t2[2];
#pragma unroll
    for (int j = 0; j < 2; j++) {
        float send = hiB ? t4[j] : t4[j + 2];
        float recv = __shfl_xor_sync(FULL, send, 2);
        t2[j] = (hiB ? t4[j + 2] : t4[j]) + recv;
    }
    bool hiC = (lane & 1) != 0;
    {
        float send = hiC ? t2[0] : t2[1];
        float recv = __shfl_xor_sync(FULL, send, 1);
        float r = (hiC ? t2[1] : t2[0]) + recv;
        out[(size_t)lig * NN + node] = r;   // lane lig holds batch b = lig
    }
}

// ---------------------------------------------------------------------------
// Launch. Inputs resolved BY SIZE (element counts are distinct):
//   fs:      B*N*D  = 2,400,000
//   weights: N*D*M  = 9,600,000
//   idx:     N*M    = 3,200,000
// ---------------------------------------------------------------------------
extern "C" void kernel_launch(void* const* d_in, const int* in_sizes, int n_in,
                              void* d_out, int out_size) {
    const float* fs  = nullptr;
    const float* w   = nullptr;
    const int*   idx = nullptr;

    for (int i = 0; i < n_in; i++) {
        if (in_sizes[i] == BB * NN * DD)      fs  = (const float*)d_in[i];
        else if (in_sizes[i] == NN * DD * MM) w   = (const float*)d_in[i];
        else if (in_sizes[i] == NN * MM)      idx = (const int*)d_in[i];
    }
    if (!fs)  fs  = (const float*)d_in[0];
    if (!w)   w   = (const float*)d_in[1];
    if (!idx) idx = (const int*)d_in[2];

    float* out = (float*)d_out;

    detect_idx_kernel<<<1, 1>>>(idx);

    int t_threads = NN * DD;
    transpose_fs_kernel<<<(t_threads + 255) / 256, 256>>>(fs);

    int m_threads = NN * 8;
    rbffd_main_kernel<<<(m_threads + 255) / 256, 256>>>(w, idx, out);
}

// round 4
// speedup vs baseline: 1.9240x; 1.9240x over previous
#include <cuda_runtime.h>

#define NN 100000
#define MM 32
#define DD 3
#define BB 8

// fs transposed to [n][d][b], rows padded to 128 B (8 float4; slots 6,7 unused)
// so each node row sits in exactly one 128B line.
__device__ __align__(128) float4 g_fst4[NN * 8];

// 1 if stencil buffer is int64, 0 if int32 (jax x64-disabled downgrade).
__device__ int g_idx_is64;

// ---------------------------------------------------------------------------
// Kernel 1: transpose fs (B,N,D) -> fs_t rows; thread 0 also detects idx dtype.
// ---------------------------------------------------------------------------
__global__ void __launch_bounds__(256) transpose_fs_kernel(
    const float* __restrict__ fs, const int* __restrict__ idx32)
{
    int t = blockIdx.x * 256 + threadIdx.x;   // t = n*3 + d
    if (t == 0) {
        int all_zero = 1;
#pragma unroll
        for (int k = 0; k < 64; k++)
            if (idx32[2 * k + 1] != 0) { all_zero = 0; break; }
        g_idx_is64 = all_zero;
    }
    if (t >= NN * DD) return;
    float v[BB];
#pragma unroll
    for (int b = 0; b < BB; b++) v[b] = __ldg(fs + (size_t)b * (NN * DD) + t);
    int n = t / DD;
    int d = t - n * DD;
    float4* dst = g_fst4 + (size_t)n * 8 + d * 2;
    dst[0] = make_float4(v[0], v[1], v[2], v[3]);
    dst[1] = make_float4(v[4], v[5], v[6], v[7]);
}

// ---------------------------------------------------------------------------
// Kernel 2: main gather + contraction, cooperative row loads.
// 8 lanes per node. Lane j: d = j>>1, batch-half = j&1 (lanes 6,7 idle on FMA).
// Per m: broadcast idx via width-8 shfl, the group loads ONE 128B row
// cooperatively (1 line / group / instruction), 4 FMAs per lane.
// Reduction over d: 2-stage width-8 butterfly (lanes 6,7 contribute zeros).
// ---------------------------------------------------------------------------
__global__ void __launch_bounds__(256, 4) rbffd_main_kernel(
    const float* __restrict__ w,        // (N, D, M) f32
    const int* __restrict__ idx32,      // (N, M) int32 or int64 pairs
    float* __restrict__ out)            // (B, N) f32
{
    const unsigned FULL = 0xffffffffu;
    int tid  = blockIdx.x * 256 + threadIdx.x;
    int node = tid >> 3;
    if (node >= NN) return;
    int j = threadIdx.x & 7;            // lane within node group

    // --- preload this lane's 4 stencil indices (m = 4j .. 4j+3), clamped ---
    int myidx[4];
    if (g_idx_is64) {
        const int* irow = idx32 + (size_t)node * MM * 2;
#pragma unroll
        for (int q = 0; q < 4; q++) {
            int v = __ldg(irow + (4 * j + q) * 2);
            myidx[q] = ((unsigned)v < (unsigned)NN) ? v : 0;
        }
    } else {
        const int4 vi = __ldg((const int4*)(idx32 + (size_t)node * MM + 4 * j));
        myidx[0] = ((unsigned)vi.x < (unsigned)NN) ? vi.x : 0;
        myidx[1] = ((unsigned)vi.y < (unsigned)NN) ? vi.y : 0;
        myidx[2] = ((unsigned)vi.z < (unsigned)NN) ? vi.z : 0;
        myidx[3] = ((unsigned)vi.w < (unsigned)NN) ? vi.w : 0;
    }

    const int  dj     = j >> 1;
    const bool active = (j < 6);
    // lane j's weight row: w[node][dj][0..31] (lanes 6,7 read d2 harmlessly)
    const float* wrow = w + (size_t)node * (DD * MM) + (dj < DD ? dj : 2) * MM;

    float4 acc = make_float4(0.f, 0.f, 0.f, 0.f);

#pragma unroll
    for (int mo = 0; mo < 4; mo++) {
        // weights for m = 8*mo .. 8*mo+7 (aligned float4 pairs)
        float4 wa = __ldg((const float4*)(wrow + 8 * mo));
        float4 wb = __ldg((const float4*)(wrow + 8 * mo + 4));
        float wv[8] = {wa.x, wa.y, wa.z, wa.w, wb.x, wb.y, wb.z, wb.w};

#pragma unroll
        for (int mi = 0; mi < 8; mi++) {
            const int m   = 8 * mo + mi;
            const int src = m >> 2;                       // group lane owning idx m
            int ridx = __shfl_sync(FULL, myidx[m & 3], src, 8);
            float4 val = make_float4(0.f, 0.f, 0.f, 0.f);
            if (active)
                val = __ldg(g_fst4 + (size_t)ridx * 8 + j);   // 16B of one shared 128B row
            const float wm = wv[mi];
            acc.x += wm * val.x;
            acc.y += wm * val.y;
            acc.z += wm * val.z;
            acc.w += wm * val.w;
        }
    }

    // --- reduce over d within the group (same batch-half = same lane parity) ---
    acc.x += __shfl_xor_sync(FULL, acc.x, 2, 8);
    acc.y += __shfl_xor_sync(FULL, acc.y, 2, 8);
    acc.z += __shfl_xor_sync(FULL, acc.z, 2, 8);
    acc.w += __shfl_xor_sync(FULL, acc.w, 2, 8);
    acc.x += __shfl_xor_sync(FULL, acc.x, 4, 8);
    acc.y += __shfl_xor_sync(FULL, acc.y, 4, 8);
    acc.z += __shfl_xor_sync(FULL, acc.z, 4, 8);
    acc.w += __shfl_xor_sync(FULL, acc.w, 4, 8);

    if (j < 2) {                                   // lane 0: b0-3, lane 1: b4-7
        const size_t b0 = (size_t)(4 * j);
        out[(b0 + 0) * NN + node] = acc.x;
        out[(b0 + 1) * NN + node] = acc.y;
        out[(b0 + 2) * NN + node] = acc.z;
        out[(b0 + 3) * NN + node] = acc.w;
    }
}

// ---------------------------------------------------------------------------
// Launch. Inputs resolved BY SIZE (element counts distinct):
//   fs = 2,400,000   weights = 9,600,000   idx = 3,200,000
// ---------------------------------------------------------------------------
extern "C" void kernel_launch(void* const* d_in, const int* in_sizes, int n_in,
                              void* d_out, int out_size) {
    const float* fs  = nullptr;
    const float* w   = nullptr;
    const int*   idx = nullptr;

    for (int i = 0; i < n_in; i++) {
        if (in_sizes[i] == BB * NN * DD)      fs  = (const float*)d_in[i];
        else if (in_sizes[i] == NN * DD * MM) w   = (const float*)d_in[i];
        else if (in_sizes[i] == NN * MM)      idx = (const int*)d_in[i];
    }
    if (!fs)  fs  = (const float*)d_in[0];
    if (!w)   w   = (const float*)d_in[1];
    if (!idx) idx = (const int*)d_in[2];

    float* out = (float*)d_out;

    int t_threads = NN * DD;
    transpose_fs_kernel<<<(t_threads + 255) / 256, 256>>>(fs, idx);

    int m_threads = NN * 8;                     // exactly 3125 blocks of 256
    rbffd_main_kernel<<<m_threads / 256, 256>>>(w, idx, out);
}

// round 5
// speedup vs baseline: 2.1776x; 1.1318x over previous
#include <cuda_runtime.h>

#define NN 100000
#define MM 32
#define DD 3
#define BB 8

// fs transposed to [n][d][b], rows padded to 128 B (8 float4; slots 6,7 unused)
// so each node row sits in exactly one 128B line.
__device__ __align__(128) float4 g_fst4[NN * 8];

// 1 if stencil buffer is int64, 0 if int32 (jax x64-disabled downgrade).
__device__ int g_idx_is64;

// ---------------------------------------------------------------------------
// Kernel 1: transpose fs (B,N,D) -> fs_t rows; thread 0 also detects idx dtype.
// ---------------------------------------------------------------------------
__global__ void __launch_bounds__(256) transpose_fs_kernel(
    const float* __restrict__ fs, const int* __restrict__ idx32)
{
    int t = blockIdx.x * 256 + threadIdx.x;   // t = n*3 + d
    if (t == 0) {
        int all_zero = 1;
#pragma unroll
        for (int k = 0; k < 64; k++)
            if (idx32[2 * k + 1] != 0) { all_zero = 0; break; }
        g_idx_is64 = all_zero;
    }
    if (t >= NN * DD) return;
    float v[BB];
#pragma unroll
    for (int b = 0; b < BB; b++) v[b] = __ldg(fs + (size_t)b * (NN * DD) + t);
    int n = t / DD;
    int d = t - n * DD;
    float4* dst = g_fst4 + (size_t)n * 8 + d * 2;
    dst[0] = make_float4(v[0], v[1], v[2], v[3]);
    dst[1] = make_float4(v[4], v[5], v[6], v[7]);
}

// ---------------------------------------------------------------------------
// Kernel 2: gather + contraction.
// Block = 256 threads = 32 nodes (8 lanes/node).
// Weights staged via smem: block loads its 32x96-float chunk fully coalesced,
// lanes then read from a bank-padded smem layout (node stride 116 words ==20
// mod 32, d stride 36 == 4 mod 32 -> <=2-way conflicts on LDS.128).
// Gather: per m one 128B fs_t row read cooperatively by the 6 active lanes.
// ---------------------------------------------------------------------------
#define PN 116   // padded words per node in smem
#define PD 36    // padded words per d-row

__global__ void __launch_bounds__(256, 4) rbffd_main_kernel(
    const float* __restrict__ w,        // (N, D, M) f32
    const int* __restrict__ idx32,      // (N, M) int32 or int64 pairs
    float* __restrict__ out)            // (B, N) f32
{
    const unsigned FULL = 0xffffffffu;
    __shared__ __align__(16) float s_w[32 * PN];   // 14848 B

    const int node0  = blockIdx.x * 32;
    const int nodeL  = threadIdx.x >> 3;           // 0..31 local node
    const int node   = node0 + nodeL;
    const int j      = threadIdx.x & 7;            // lane in node group

    // --- stage this block's weights: 768 float4, coalesced ---
    {
        const float4* wsrc = (const float4*)(w + (size_t)node0 * (DD * MM));
#pragma unroll
        for (int p = 0; p < 3; p++) {
            int q = threadIdx.x + p * 256;         // float4 index 0..767
            float4 v = __ldg(wsrc + q);
            int nl = q / 24;                       // node local
            int r  = q % 24;
            int dj = r >> 3;                       // d row
            int m4 = r & 7;                        // float4 within row
            *(float4*)(s_w + nl * PN + dj * PD + m4 * 4) = v;
        }
    }

    // --- preload this lane's 4 stencil indices (m = 4j .. 4j+3), clamped ---
    int myidx[4];
    if (g_idx_is64) {
        const int* irow = idx32 + (size_t)node * MM * 2;
#pragma unroll
        for (int q = 0; q < 4; q++) {
            int v = __ldg(irow + (4 * j + q) * 2);
            myidx[q] = ((unsigned)v < (unsigned)NN) ? v : 0;
        }
    } else {
        const int4 vi = __ldg((const int4*)(idx32 + (size_t)node * MM + 4 * j));
        myidx[0] = ((unsigned)vi.x < (unsigned)NN) ? vi.x : 0;
        myidx[1] = ((unsigned)vi.y < (unsigned)NN) ? vi.y : 0;
        myidx[2] = ((unsigned)vi.z < (unsigned)NN) ? vi.z : 0;
        myidx[3] = ((unsigned)vi.w < (unsigned)NN) ? vi.w : 0;
    }

    __syncthreads();

    const int  dj     = j >> 1;
    const bool active = (j < 6);
    const float* wl = s_w + nodeL * PN + (dj < DD ? dj : 2) * PD;

    float4 acc = make_float4(0.f, 0.f, 0.f, 0.f);

#pragma unroll
    for (int mo = 0; mo < 4; mo++) {
        float4 wa = *(const float4*)(wl + 8 * mo);
        float4 wb = *(const float4*)(wl + 8 * mo + 4);
        float wv[8] = {wa.x, wa.y, wa.z, wa.w, wb.x, wb.y, wb.z, wb.w};

#pragma unroll
        for (int mi = 0; mi < 8; mi++) {
            const int m   = 8 * mo + mi;
            const int src = m >> 2;                       // group lane owning idx m
            int ridx = __shfl_sync(FULL, myidx[m & 3], src, 8);
            float4 val = make_float4(0.f, 0.f, 0.f, 0.f);
            if (active)
                val = __ldg(g_fst4 + (size_t)ridx * 8 + j);   // 16B of shared 128B row
            const float wm = wv[mi];
            acc.x += wm * val.x;
            acc.y += wm * val.y;
            acc.z += wm * val.z;
            acc.w += wm * val.w;
        }
    }

    // --- reduce over d within the group (same batch-half = same lane parity) ---
    acc.x += __shfl_xor_sync(FULL, acc.x, 2, 8);
    acc.y += __shfl_xor_sync(FULL, acc.y, 2, 8);
    acc.z += __shfl_xor_sync(FULL, acc.z, 2, 8);
    acc.w += __shfl_xor_sync(FULL, acc.w, 2, 8);
    acc.x += __shfl_xor_sync(FULL, acc.x, 4, 8);
    acc.y += __shfl_xor_sync(FULL, acc.y, 4, 8);
    acc.z += __shfl_xor_sync(FULL, acc.z, 4, 8);
    acc.w += __shfl_xor_sync(FULL, acc.w, 4, 8);

    if (j < 2) {                                   // lane 0: b0-3, lane 1: b4-7
        const size_t b0 = (size_t)(4 * j);
        out[(b0 + 0) * NN + node] = acc.x;
        out[(b0 + 1) * NN + node] = acc.y;
        out[(b0 + 2) * NN + node] = acc.z;
        out[(b0 + 3) * NN + node] = acc.w;
    }
}

// ---------------------------------------------------------------------------
// Launch. Inputs resolved BY SIZE (element counts distinct):
//   fs = 2,400,000   weights = 9,600,000   idx = 3,200,000
// ---------------------------------------------------------------------------
extern "C" void kernel_launch(void* const* d_in, const int* in_sizes, int n_in,
                              void* d_out, int out_size) {
    const float* fs  = nullptr;
    const float* w   = nullptr;
    const int*   idx = nullptr;

    for (int i = 0; i < n_in; i++) {
        if (in_sizes[i] == BB * NN * DD)      fs  = (const float*)d_in[i];
        else if (in_sizes[i] == NN * DD * MM) w   = (const float*)d_in[i];
        else if (in_sizes[i] == NN * MM)      idx = (const int*)d_in[i];
    }
    if (!fs)  fs  = (const float*)d_in[0];
    if (!w)   w   = (const float*)d_in[1];
    if (!idx) idx = (const int*)d_in[2];

    float* out = (float*)d_out;

    int t_threads = NN * DD;
    transpose_fs_kernel<<<(t_threads + 255) / 256, 256>>>(fs, idx);

    rbffd_main_kernel<<<NN / 32, 256>>>(w, idx, out);   // 3125 blocks
}